// round 1
// baseline (speedup 1.0000x reference)
#include <cuda_runtime.h>
#include <math.h>

#define C   64
#define HW  64
#define NSP 4096          // N = HW*HW spatial positions
#define BB  8             // batch
#define EPSBN 1e-5f

#define TN 32             // query rows per CTA
#define TM 32             // key/value chunk
#define QNP 36            // qn pitch (floats), 16B-aligned float4 rows
#define QMP 33            // qm/vm pitch, kills 4-way bank conflict on d-strided reads
#define PP  36            // p pitch

// scratch (no allocations allowed -> device globals)
__device__ float g_V[BB * C * NSP];     // after conv1+bn1+relu
__device__ float g_attn[BB * C * NSP];  // attention output
__device__ float g_U[BB * C * NSP];     // after depthwise+bn2+relu

// ---------------------------------------------------------------------------
// conv1x1 (w1) + BN1 + ReLU  ->  g_V
// ---------------------------------------------------------------------------
__global__ __launch_bounds__(256) void conv1_kernel(
    const float* __restrict__ x, const float* __restrict__ w1,
    const float* __restrict__ g, const float* __restrict__ bb,
    const float* __restrict__ m, const float* __restrict__ v)
{
    __shared__ float ws[C * C];
    int tid = threadIdx.x;
    for (int i = tid; i < C * C; i += 256) ws[i] = w1[i];
    __syncthreads();

    int b = blockIdx.y;
    int n = blockIdx.x * 256 + tid;
    const float* xp = x + (size_t)b * C * NSP + n;
    float xv[C];
#pragma unroll
    for (int c = 0; c < C; c++) xv[c] = xp[(size_t)c * NSP];

    float* op = g_V + (size_t)b * C * NSP + n;
    for (int o = 0; o < C; o++) {
        float a0 = 0.f, a1 = 0.f, a2 = 0.f, a3 = 0.f;
#pragma unroll
        for (int c = 0; c < C; c += 4) {
            a0 += ws[o * C + c + 0] * xv[c + 0];
            a1 += ws[o * C + c + 1] * xv[c + 1];
            a2 += ws[o * C + c + 2] * xv[c + 2];
            a3 += ws[o * C + c + 3] * xv[c + 3];
        }
        float acc = (a0 + a1) + (a2 + a3);
        float inv = g[o] * rsqrtf(v[o] + EPSBN);
        float r = acc * inv + (bb[o] - m[o] * inv);
        op[(size_t)o * NSP] = fmaxf(r, 0.f);
    }
}

// ---------------------------------------------------------------------------
// flash-style attention: Q=K=x, V=g_V, scale 1/8, softmax over m -> g_attn
// one CTA = (batch b, 32 query rows), streams 32-wide K/V chunks
// ---------------------------------------------------------------------------
__global__ __launch_bounds__(256) void attn_kernel(const float* __restrict__ x)
{
    __shared__ float qn[C * QNP];               // [d][i]
    __shared__ float qm[C * QMP];               // [d][j]
    __shared__ float vm[C * QMP];               // [d][j]
    __shared__ float p[TM * PP];                // [j][i]  (S then P, transposed)
    __shared__ __align__(16) float smax[TN];
    __shared__ __align__(16) float ssum[TN];
    __shared__ __align__(16) float scal[TN];

    int tid = threadIdx.x;
    int b = blockIdx.y;
    int n0 = blockIdx.x * TN;
    const float* xb = x + (size_t)b * C * NSP;
    const float* vb = g_V + (size_t)b * C * NSP;

    // load Q tile for these 32 rows
    {
        int i = tid % TN, dq = tid / TN;        // dq in 0..7
#pragma unroll
        for (int k = 0; k < 8; k++) {
            int d = dq * 8 + k;
            qn[d * QNP + i] = xb[(size_t)d * NSP + n0 + i];
        }
    }
    if (tid < TN) { smax[tid] = -1e30f; ssum[tid] = 0.f; }

    // tiling maps
    const int s_i0 = (tid % 8) * 4;             // S: 4(i) x 1(j) per thread
    const int s_j  = tid / 8;
    const int o_i0 = (tid % 8) * 4;             // PV: 2(d) x 4(i) per thread
    const int o_d0 = (tid / 8) * 2;

    float o00 = 0.f, o01 = 0.f, o02 = 0.f, o03 = 0.f;
    float o10 = 0.f, o11 = 0.f, o12 = 0.f, o13 = 0.f;

    __syncthreads();

    for (int m0 = 0; m0 < NSP; m0 += TM) {
        // ---- load K/V chunk ----
        {
            int j = tid % TM, dq = tid / TM;
#pragma unroll
            for (int k = 0; k < 8; k++) {
                int d = dq * 8 + k;
                qm[d * QMP + j] = xb[(size_t)d * NSP + m0 + j];
                vm[d * QMP + j] = vb[(size_t)d * NSP + m0 + j];
            }
        }
        __syncthreads();

        // ---- S = Qn^T Qm / 8, stored transposed p[j][i] ----
        {
            float a0 = 0.f, a1 = 0.f, a2 = 0.f, a3 = 0.f;
#pragma unroll
            for (int d = 0; d < C; d++) {
                float qmv = qm[d * QMP + s_j];
                float4 qv = *(const float4*)&qn[d * QNP + s_i0];
                a0 += qv.x * qmv; a1 += qv.y * qmv;
                a2 += qv.z * qmv; a3 += qv.w * qmv;
            }
            const float sc = 0.125f;
            float4 sv = make_float4(a0 * sc, a1 * sc, a2 * sc, a3 * sc);
            *(float4*)&p[s_j * PP + s_i0] = sv;
        }
        __syncthreads();

        // ---- online softmax: warp w owns rows 4w..4w+3, 8 lanes per row ----
        {
            int lane = tid & 31, w = tid >> 5;
            int row = w * 4 + (lane >> 3);
            int jb = lane & 7;
            float mx = -1e30f;
#pragma unroll
            for (int k = 0; k < 4; k++)
                mx = fmaxf(mx, p[(jb + k * 8) * PP + row]);
            mx = fmaxf(mx, __shfl_xor_sync(0xffffffffu, mx, 1));
            mx = fmaxf(mx, __shfl_xor_sync(0xffffffffu, mx, 2));
            mx = fmaxf(mx, __shfl_xor_sync(0xffffffffu, mx, 4));
            float mold = smax[row];
            float mnew = fmaxf(mold, mx);
            float cexp = __expf(mold - mnew);
            float s = 0.f;
#pragma unroll
            for (int k = 0; k < 4; k++) {
                int idx = (jb + k * 8) * PP + row;
                float e = __expf(p[idx] - mnew);
                p[idx] = e;
                s += e;
            }
            s += __shfl_xor_sync(0xffffffffu, s, 1);
            s += __shfl_xor_sync(0xffffffffu, s, 2);
            s += __shfl_xor_sync(0xffffffffu, s, 4);
            if (jb == 0) {
                smax[row] = mnew;
                ssum[row] = ssum[row] * cexp + s;
                scal[row] = cexp;
            }
        }
        __syncthreads();

        // ---- O = O*c + P V ----
        {
            float4 cv = *(const float4*)&scal[o_i0];
            o00 *= cv.x; o01 *= cv.y; o02 *= cv.z; o03 *= cv.w;
            o10 *= cv.x; o11 *= cv.y; o12 *= cv.z; o13 *= cv.w;
#pragma unroll
            for (int j = 0; j < TM; j++) {
                float v0 = vm[(o_d0 + 0) * QMP + j];
                float v1 = vm[(o_d0 + 1) * QMP + j];
                float4 pv = *(const float4*)&p[j * PP + o_i0];
                o00 += v0 * pv.x; o01 += v0 * pv.y; o02 += v0 * pv.z; o03 += v0 * pv.w;
                o10 += v1 * pv.x; o11 += v1 * pv.y; o12 += v1 * pv.z; o13 += v1 * pv.w;
            }
        }
        __syncthreads();
    }

    // ---- normalize and write ----
    {
        float4 lv = *(const float4*)&ssum[o_i0];
        float r0 = 1.f / lv.x, r1 = 1.f / lv.y, r2 = 1.f / lv.z, r3 = 1.f / lv.w;
        float* ob = g_attn + (size_t)b * C * NSP + n0 + o_i0;
        float* o0 = ob + (size_t)(o_d0 + 0) * NSP;
        float* o1 = ob + (size_t)(o_d0 + 1) * NSP;
        o0[0] = o00 * r0; o0[1] = o01 * r1; o0[2] = o02 * r2; o0[3] = o03 * r3;
        o1[0] = o10 * r0; o1[1] = o11 * r1; o1[2] = o12 * r2; o1[3] = o13 * r3;
    }
}

// ---------------------------------------------------------------------------
// depthwise 3x3 SAME (w2) + BN2 + ReLU : g_attn -> g_U
// ---------------------------------------------------------------------------
__global__ __launch_bounds__(256) void dw_kernel(
    const float* __restrict__ w2,
    const float* __restrict__ g, const float* __restrict__ bb,
    const float* __restrict__ m, const float* __restrict__ v)
{
    int idx = blockIdx.x * 256 + threadIdx.x;      // over BB*C*NSP
    int xw = idx & (HW - 1);
    int rest = idx >> 6;
    int y = rest & (HW - 1);
    rest >>= 6;
    int c = rest & (C - 1);
    const float* ip = g_attn + (size_t)(idx - (y * HW + xw) - 0) ; // base of this (b,c) plane:
    ip = g_attn + ((size_t)(idx >> 12) << 12);     // idx/4096*4096
    float acc = 0.f;
#pragma unroll
    for (int dy = -1; dy <= 1; dy++) {
        int yy = y + dy;
        if (yy < 0 || yy >= HW) continue;
#pragma unroll
        for (int dx = -1; dx <= 1; dx++) {
            int xx = xw + dx;
            if (xx < 0 || xx >= HW) continue;
            acc += ip[yy * HW + xx] * w2[c * 9 + (dy + 1) * 3 + (dx + 1)];
        }
    }
    float inv = g[c] * rsqrtf(v[c] + EPSBN);
    float r = acc * inv + (bb[c] - m[c] * inv);
    g_U[idx] = fmaxf(r, 0.f);
}

// ---------------------------------------------------------------------------
// conv1x1 (w3) + BN3 + residual(x) -> out
// ---------------------------------------------------------------------------
__global__ __launch_bounds__(256) void conv3_kernel(
    const float* __restrict__ w3,
    const float* __restrict__ g, const float* __restrict__ bb,
    const float* __restrict__ m, const float* __restrict__ v,
    const float* __restrict__ x, float* __restrict__ out)
{
    __shared__ float ws[C * C];
    int tid = threadIdx.x;
    for (int i = tid; i < C * C; i += 256) ws[i] = w3[i];
    __syncthreads();

    int b = blockIdx.y;
    int n = blockIdx.x * 256 + tid;
    const float* up = g_U + (size_t)b * C * NSP + n;
    float uv[C];
#pragma unroll
    for (int c = 0; c < C; c++) uv[c] = up[(size_t)c * NSP];

    const float* xp = x + (size_t)b * C * NSP + n;
    float* op = out + (size_t)b * C * NSP + n;
    for (int o = 0; o < C; o++) {
        float a0 = 0.f, a1 = 0.f, a2 = 0.f, a3 = 0.f;
#pragma unroll
        for (int c = 0; c < C; c += 4) {
            a0 += ws[o * C + c + 0] * uv[c + 0];
            a1 += ws[o * C + c + 1] * uv[c + 1];
            a2 += ws[o * C + c + 2] * uv[c + 2];
            a3 += ws[o * C + c + 3] * uv[c + 3];
        }
        float acc = (a0 + a1) + (a2 + a3);
        float inv = g[o] * rsqrtf(v[o] + EPSBN);
        float r = acc * inv + (bb[o] - m[o] * inv) + xp[(size_t)o * NSP];
        op[(size_t)o * NSP] = r;
    }
}

// ---------------------------------------------------------------------------
extern "C" void kernel_launch(void* const* d_in, const int* in_sizes, int n_in,
                              void* d_out, int out_size)
{
    const float* x    = (const float*)d_in[0];
    const float* w1   = (const float*)d_in[1];
    const float* bn1g = (const float*)d_in[2];
    const float* bn1b = (const float*)d_in[3];
    const float* bn1m = (const float*)d_in[4];
    const float* bn1v = (const float*)d_in[5];
    const float* w2   = (const float*)d_in[6];
    const float* bn2g = (const float*)d_in[7];
    const float* bn2b = (const float*)d_in[8];
    const float* bn2m = (const float*)d_in[9];
    const float* bn2v = (const float*)d_in[10];
    const float* w3   = (const float*)d_in[11];
    const float* bn3g = (const float*)d_in[12];
    const float* bn3b = (const float*)d_in[13];
    const float* bn3m = (const float*)d_in[14];
    const float* bn3v = (const float*)d_in[15];
    float* out = (float*)d_out;

    conv1_kernel<<<dim3(NSP / 256, BB), 256>>>(x, w1, bn1g, bn1b, bn1m, bn1v);
    attn_kernel<<<dim3(NSP / TN, BB), 256>>>(x);
    dw_kernel<<<(BB * C * NSP) / 256, 256>>>(w2, bn2g, bn2b, bn2m, bn2v);
    conv3_kernel<<<dim3(NSP / 256, BB), 256>>>(w3, bn3g, bn3b, bn3m, bn3v, x, out);
}

// round 2
// speedup vs baseline: 5.1369x; 5.1369x over previous
#include <cuda_runtime.h>
#include <math.h>

#define C   64
#define HW  64
#define NSP 4096          // N = HW*HW spatial positions
#define BB  8             // batch
#define EPSBN 1e-5f

// attention tiling
#define TNQ 128           // query rows per CTA
#define TMK 64            // key/value chunk
#define PQ  136           // Q smem pitch (d-major [64][128])  -> banks 8q+g distinct
#define PK  72            // K smem pitch (d-major [64][64])   -> banks 8q+g distinct
#define PVP 68            // V smem pitch (d-major [64][64])   -> banks 4g+q distinct
#define SMEM_U32 (64*PQ + 64*PK + 64*PVP)   // 17664 u32 = 70656 B

// scratch (no allocations allowed -> device globals)
__device__ float g_V[BB * C * NSP];     // after conv1+bn1+relu
__device__ float g_attn[BB * C * NSP];  // attention output
__device__ float g_U[BB * C * NSP];     // after depthwise+bn2+relu

// ---------------------------------------------------------------------------
// helpers
// ---------------------------------------------------------------------------
__device__ __forceinline__ unsigned f2tf32(float f) {
    unsigned u;
    asm("cvt.rna.tf32.f32 %0, %1;" : "=r"(u) : "f"(f));
    return u;
}

__device__ __forceinline__ void mma_tf32(float c[4],
                                         unsigned a0, unsigned a1, unsigned a2, unsigned a3,
                                         unsigned b0, unsigned b1) {
    asm volatile(
        "mma.sync.aligned.m16n8k8.row.col.f32.tf32.tf32.f32 "
        "{%0,%1,%2,%3},{%4,%5,%6,%7},{%8,%9},{%0,%1,%2,%3};\n"
        : "+f"(c[0]), "+f"(c[1]), "+f"(c[2]), "+f"(c[3])
        : "r"(a0), "r"(a1), "r"(a2), "r"(a3), "r"(b0), "r"(b1));
}

// ---------------------------------------------------------------------------
// conv1x1 (w1) + BN1 + ReLU  ->  g_V
// ---------------------------------------------------------------------------
__global__ __launch_bounds__(128) void conv1_kernel(
    const float* __restrict__ x, const float* __restrict__ w1,
    const float* __restrict__ g, const float* __restrict__ bb,
    const float* __restrict__ m, const float* __restrict__ v)
{
    __shared__ float ws[C * C];
    int tid = threadIdx.x;
    for (int i = tid; i < C * C; i += 128) ws[i] = w1[i];
    __syncthreads();

    int b = blockIdx.y;
    int n = blockIdx.x * 128 + tid;
    const float* xp = x + (size_t)b * C * NSP + n;
    float xv[C];
#pragma unroll
    for (int c = 0; c < C; c++) xv[c] = xp[(size_t)c * NSP];

    float* op = g_V + (size_t)b * C * NSP + n;
    for (int o = 0; o < C; o++) {
        float a0 = 0.f, a1 = 0.f, a2 = 0.f, a3 = 0.f;
#pragma unroll
        for (int c = 0; c < C; c += 4) {
            a0 += ws[o * C + c + 0] * xv[c + 0];
            a1 += ws[o * C + c + 1] * xv[c + 1];
            a2 += ws[o * C + c + 2] * xv[c + 2];
            a3 += ws[o * C + c + 3] * xv[c + 3];
        }
        float acc = (a0 + a1) + (a2 + a3);
        float inv = g[o] * rsqrtf(v[o] + EPSBN);
        float r = acc * inv + (bb[o] - m[o] * inv);
        op[(size_t)o * NSP] = fmaxf(r, 0.f);
    }
}

// ---------------------------------------------------------------------------
// flash attention with tf32 mma.sync: Q=K=x (scale folded into Q), V=g_V
// CTA = (batch, 128 query rows); 8 warps; warp owns 16 rows x all 64 cols of S
// ---------------------------------------------------------------------------
__global__ __launch_bounds__(256, 2) void attn_mma_kernel(const float* __restrict__ x)
{
    extern __shared__ unsigned smem_u[];
    unsigned* Qu = smem_u;            // [d][i]  64 x 128, pitch PQ
    unsigned* Ku = Qu + 64 * PQ;      // [d][j]  64 x 64,  pitch PK
    unsigned* Vu = Ku + 64 * PK;      // [d][j]  64 x 64,  pitch PVP

    const int tid  = threadIdx.x;
    const int lane = tid & 31;
    const int wid  = tid >> 5;
    const int g    = lane >> 2;       // group id 0..7
    const int q    = lane & 3;        // 0..3
    const int i0   = wid * 16;        // warp's row base within CTA tile

    const int b  = blockIdx.y;
    const int n0 = blockIdx.x * TNQ;
    const float* xb = x   + (size_t)b * C * NSP;
    const float* vb = g_V + (size_t)b * C * NSP;

    // load Q tile (scale 1/8 folded in)
    for (int idx = tid; idx < 64 * TNQ; idx += 256) {
        int d = idx >> 7, i = idx & 127;
        Qu[d * PQ + i] = f2tf32(xb[(size_t)d * NSP + n0 + i] * 0.125f);
    }

    float SC[8][4];                   // S / P fragments (warp's 16 x 64 tile)
    float OC[8][4];                   // O accumulators   (16 rows x 64 dims)
#pragma unroll
    for (int t = 0; t < 8; t++) { OC[t][0] = OC[t][1] = OC[t][2] = OC[t][3] = 0.f; }
    float rm0 = -1e30f, rm1 = -1e30f; // running row max (rows g, g+8)
    float rl0 = 0.f,    rl1 = 0.f;    // running row sum

    for (int m0 = 0; m0 < NSP; m0 += TMK) {
        __syncthreads();              // prev PV done; Q ready on first iter
        // ---- load K/V chunk (coalesced d-major) ----
        for (int idx = tid; idx < 64 * TMK; idx += 256) {
            int d = idx >> 6, j = idx & 63;
            Ku[d * PK  + j] = f2tf32(xb[(size_t)d * NSP + m0 + j]);
            Vu[d * PVP + j] = f2tf32(vb[(size_t)d * NSP + m0 + j]);
        }
        __syncthreads();

        // ---- S = Q K^T (already scaled) ----
#pragma unroll
        for (int t = 0; t < 8; t++) { SC[t][0] = SC[t][1] = SC[t][2] = SC[t][3] = 0.f; }
#pragma unroll
        for (int kt = 0; kt < 8; kt++) {
            int r = kt * 8 + q;
            unsigned a0 = Qu[r * PQ + i0 + g];
            unsigned a1 = Qu[r * PQ + i0 + g + 8];
            unsigned a2 = Qu[(r + 4) * PQ + i0 + g];
            unsigned a3 = Qu[(r + 4) * PQ + i0 + g + 8];
#pragma unroll
            for (int nt = 0; nt < 8; nt++) {
                unsigned b0 = Ku[r * PK + nt * 8 + g];
                unsigned b1 = Ku[(r + 4) * PK + nt * 8 + g];
                mma_tf32(SC[nt], a0, a1, a2, a3, b0, b1);
            }
        }

        // ---- online softmax (rows g and g+8; 4 lanes per row share via shfl) ----
        float mx0 = -1e30f, mx1 = -1e30f;
#pragma unroll
        for (int nt = 0; nt < 8; nt++) {
            mx0 = fmaxf(mx0, fmaxf(SC[nt][0], SC[nt][1]));
            mx1 = fmaxf(mx1, fmaxf(SC[nt][2], SC[nt][3]));
        }
        mx0 = fmaxf(mx0, __shfl_xor_sync(0xffffffffu, mx0, 1));
        mx0 = fmaxf(mx0, __shfl_xor_sync(0xffffffffu, mx0, 2));
        mx1 = fmaxf(mx1, __shfl_xor_sync(0xffffffffu, mx1, 1));
        mx1 = fmaxf(mx1, __shfl_xor_sync(0xffffffffu, mx1, 2));

        float mn0 = fmaxf(rm0, mx0), mn1 = fmaxf(rm1, mx1);
        float c0 = __expf(rm0 - mn0), c1 = __expf(rm1 - mn1);
        rm0 = mn0; rm1 = mn1;

        float ls0 = 0.f, ls1 = 0.f;
#pragma unroll
        for (int nt = 0; nt < 8; nt++) {
            SC[nt][0] = __expf(SC[nt][0] - mn0); ls0 += SC[nt][0];
            SC[nt][1] = __expf(SC[nt][1] - mn0); ls0 += SC[nt][1];
            SC[nt][2] = __expf(SC[nt][2] - mn1); ls1 += SC[nt][2];
            SC[nt][3] = __expf(SC[nt][3] - mn1); ls1 += SC[nt][3];
        }
        ls0 += __shfl_xor_sync(0xffffffffu, ls0, 1);
        ls0 += __shfl_xor_sync(0xffffffffu, ls0, 2);
        ls1 += __shfl_xor_sync(0xffffffffu, ls1, 1);
        ls1 += __shfl_xor_sync(0xffffffffu, ls1, 2);
        rl0 = rl0 * c0 + ls0;
        rl1 = rl1 * c1 + ls1;

        // rescale O
#pragma unroll
        for (int t = 0; t < 8; t++) {
            OC[t][0] *= c0; OC[t][1] *= c0;
            OC[t][2] *= c1; OC[t][3] *= c1;
        }

        // convert P fragments to tf32 bits in place
#pragma unroll
        for (int t = 0; t < 8; t++) {
            SC[t][0] = __uint_as_float(f2tf32(SC[t][0]));
            SC[t][1] = __uint_as_float(f2tf32(SC[t][1]));
            SC[t][2] = __uint_as_float(f2tf32(SC[t][2]));
            SC[t][3] = __uint_as_float(f2tf32(SC[t][3]));
        }

        // ---- O += P V : A fragments built from SC via lane permute ----
        const int base = lane & ~3;
        const int srcA = base | (q >> 1);
        const int srcB = srcA + 2;
        const bool odd = lane & 1;
#pragma unroll
        for (int jt = 0; jt < 8; jt++) {
            float p0 = SC[jt][0], p1 = SC[jt][1], p2 = SC[jt][2], p3 = SC[jt][3];
            float q0A = __shfl_sync(0xffffffffu, p0, srcA);
            float q1A = __shfl_sync(0xffffffffu, p1, srcA);
            float q2A = __shfl_sync(0xffffffffu, p2, srcA);
            float q3A = __shfl_sync(0xffffffffu, p3, srcA);
            float q0B = __shfl_sync(0xffffffffu, p0, srcB);
            float q1B = __shfl_sync(0xffffffffu, p1, srcB);
            float q2B = __shfl_sync(0xffffffffu, p2, srcB);
            float q3B = __shfl_sync(0xffffffffu, p3, srcB);
            unsigned a0 = __float_as_uint(odd ? q1A : q0A);   // row g,   col jt*8+q
            unsigned a1 = __float_as_uint(odd ? q3A : q2A);   // row g+8, col jt*8+q
            unsigned a2 = __float_as_uint(odd ? q1B : q0B);   // row g,   col jt*8+q+4
            unsigned a3 = __float_as_uint(odd ? q3B : q2B);   // row g+8, col jt*8+q+4
#pragma unroll
            for (int nt2 = 0; nt2 < 8; nt2++) {
                unsigned b0 = Vu[(nt2 * 8 + g) * PVP + jt * 8 + q];
                unsigned b1 = Vu[(nt2 * 8 + g) * PVP + jt * 8 + q + 4];
                mma_tf32(OC[nt2], a0, a1, a2, a3, b0, b1);
            }
        }
    }

    // ---- normalize + write (32B-sector-friendly scattered stores) ----
    {
        float inv0 = 1.f / rl0, inv1 = 1.f / rl1;
        float* ob = g_attn + (size_t)b * C * NSP + n0 + i0 + g;
#pragma unroll
        for (int nt2 = 0; nt2 < 8; nt2++) {
            int d0 = nt2 * 8 + 2 * q;
            ob[(size_t)d0 * NSP]           = OC[nt2][0] * inv0;
            ob[(size_t)(d0 + 1) * NSP]     = OC[nt2][1] * inv0;
            ob[(size_t)d0 * NSP + 8]       = OC[nt2][2] * inv1;
            ob[(size_t)(d0 + 1) * NSP + 8] = OC[nt2][3] * inv1;
        }
    }
}

// ---------------------------------------------------------------------------
// depthwise 3x3 SAME (w2) + BN2 + ReLU : g_attn -> g_U
// ---------------------------------------------------------------------------
__global__ __launch_bounds__(256) void dw_kernel(
    const float* __restrict__ w2,
    const float* __restrict__ g, const float* __restrict__ bb,
    const float* __restrict__ m, const float* __restrict__ v)
{
    int idx = blockIdx.x * 256 + threadIdx.x;      // over BB*C*NSP
    int xw = idx & (HW - 1);
    int rest = idx >> 6;
    int y = rest & (HW - 1);
    rest >>= 6;
    int c = rest & (C - 1);
    const float* ip = g_attn + ((size_t)(idx >> 12) << 12);  // (b,c) plane base
    float acc = 0.f;
#pragma unroll
    for (int dy = -1; dy <= 1; dy++) {
        int yy = y + dy;
        if (yy < 0 || yy >= HW) continue;
#pragma unroll
        for (int dx = -1; dx <= 1; dx++) {
            int xx = xw + dx;
            if (xx < 0 || xx >= HW) continue;
            acc += ip[yy * HW + xx] * w2[c * 9 + (dy + 1) * 3 + (dx + 1)];
        }
    }
    float inv = g[c] * rsqrtf(v[c] + EPSBN);
    float r = acc * inv + (bb[c] - m[c] * inv);
    g_U[idx] = fmaxf(r, 0.f);
}

// ---------------------------------------------------------------------------
// conv1x1 (w3) + BN3 + residual(x) -> out
// ---------------------------------------------------------------------------
__global__ __launch_bounds__(128) void conv3_kernel(
    const float* __restrict__ w3,
    const float* __restrict__ g, const float* __restrict__ bb,
    const float* __restrict__ m, const float* __restrict__ v,
    const float* __restrict__ x, float* __restrict__ out)
{
    __shared__ float ws[C * C];
    int tid = threadIdx.x;
    for (int i = tid; i < C * C; i += 128) ws[i] = w3[i];
    __syncthreads();

    int b = blockIdx.y;
    int n = blockIdx.x * 128 + tid;
    const float* up = g_U + (size_t)b * C * NSP + n;
    float uv[C];
#pragma unroll
    for (int c = 0; c < C; c++) uv[c] = up[(size_t)c * NSP];

    const float* xp = x + (size_t)b * C * NSP + n;
    float* op = out + (size_t)b * C * NSP + n;
    for (int o = 0; o < C; o++) {
        float a0 = 0.f, a1 = 0.f, a2 = 0.f, a3 = 0.f;
#pragma unroll
        for (int c = 0; c < C; c += 4) {
            a0 += ws[o * C + c + 0] * uv[c + 0];
            a1 += ws[o * C + c + 1] * uv[c + 1];
            a2 += ws[o * C + c + 2] * uv[c + 2];
            a3 += ws[o * C + c + 3] * uv[c + 3];
        }
        float acc = (a0 + a1) + (a2 + a3);
        float inv = g[o] * rsqrtf(v[o] + EPSBN);
        float r = acc * inv + (bb[o] - m[o] * inv) + xp[(size_t)o * NSP];
        op[(size_t)o * NSP] = r;
    }
}

// ---------------------------------------------------------------------------
extern "C" void kernel_launch(void* const* d_in, const int* in_sizes, int n_in,
                              void* d_out, int out_size)
{
    const float* x    = (const float*)d_in[0];
    const float* w1   = (const float*)d_in[1];
    const float* bn1g = (const float*)d_in[2];
    const float* bn1b = (const float*)d_in[3];
    const float* bn1m = (const float*)d_in[4];
    const float* bn1v = (const float*)d_in[5];
    const float* w2   = (const float*)d_in[6];
    const float* bn2g = (const float*)d_in[7];
    const float* bn2b = (const float*)d_in[8];
    const float* bn2m = (const float*)d_in[9];
    const float* bn2v = (const float*)d_in[10];
    const float* w3   = (const float*)d_in[11];
    const float* bn3g = (const float*)d_in[12];
    const float* bn3b = (const float*)d_in[13];
    const float* bn3m = (const float*)d_in[14];
    const float* bn3v = (const float*)d_in[15];
    float* out = (float*)d_out;

    static int smem_set = 0;
    if (!smem_set) {
        cudaFuncSetAttribute(attn_mma_kernel,
                             cudaFuncAttributeMaxDynamicSharedMemorySize,
                             SMEM_U32 * 4);
        smem_set = 1;
    }

    conv1_kernel<<<dim3(NSP / 128, BB), 128>>>(x, w1, bn1g, bn1b, bn1m, bn1v);
    attn_mma_kernel<<<dim3(NSP / TNQ, BB), 256, SMEM_U32 * 4>>>(x);
    dw_kernel<<<(BB * C * NSP) / 256, 256>>>(w2, bn2g, bn2b, bn2m, bn2v);
    conv3_kernel<<<dim3(NSP / 128, BB), 128>>>(w3, bn3g, bn3b, bn3m, bn3v, x, out);
}